// round 17
// baseline (speedup 1.0000x reference)
#include <cuda_runtime.h>
#include <stdint.h>

#define NN    2048         // num_nodes
#define W     64           // words per bitmask row = NN/32
#define FDIM  8            // edge feature dim
#define EB    (NN / 4)     // expand/emit blocks (4 rows each)

__device__ uint32_t g_adj     [NN * W];  // zero at load; re-zeroed by k_attr_tail
__device__ uint32_t g_comb    [NN * W];
__device__ int      g_rowcnt  [NN];
__device__ int      g_wordexcl[NN * W];  // row-local word offset
__device__ int      g_off     [NN + 1];  // global row offsets (last expand block)
__device__ int      g_ctr;               // expand completion counter (reset each call)

// ---------------------------------------------------------------------------
// init_attr: zero attr region [E_MAX, F] (streaming; gates only k_attr_tail)
// ---------------------------------------------------------------------------
__global__ void k_init_attr(float* __restrict__ out, int emax)
{
    float* base = out + (int64_t)emax * 2;
    const int64_t n4 = ((int64_t)emax * FDIM) >> 2;
    const float4 zer = make_float4(0.f, 0.f, 0.f, 0.f);
    int64_t stride = (int64_t)gridDim.x * blockDim.x;
    for (int64_t i = (int64_t)blockIdx.x * blockDim.x + threadIdx.x;
         i < n4; i += stride)
        __stcs(((float4*)base) + i, zer);
}

// ---------------------------------------------------------------------------
// scatter: set adjacency bits
// ---------------------------------------------------------------------------
__global__ void k_scatter(const int* __restrict__ src,
                          const int* __restrict__ dst, int E)
{
    int e = blockIdx.x * blockDim.x + threadIdx.x;
    if (e >= E) return;
    int s = src[e], d = dst[e];
    atomicOr(&g_adj[s * W + (d >> 5)], 1u << (d & 31));
}

// ---------------------------------------------------------------------------
// expand: comb + row-local word offsets + rowcnt; LAST block scans g_off.
// 512 blocks x 256 threads, 4 rows/block.
// ---------------------------------------------------------------------------
__global__ __launch_bounds__(256) void k_expand()
{
    __shared__ uint16_t nbr[4][NN];
    __shared__ int wtot[4][2];
    __shared__ int etot[4][2];
    __shared__ int islast;
    __shared__ int swarp[8];

    const int tid  = threadIdx.x;
    const int g    = tid >> 6;
    const int w    = tid & 63;
    const int r    = (blockIdx.x << 2) + g;
    const int lane = w & 31, hw = w >> 5;

    uint32_t a = g_adj[r * W + w];

    // word-scan of adjacency popcounts -> compaction offsets
    int pc = __popc(a);
    int x = pc;
    #pragma unroll
    for (int o = 1; o < 32; o <<= 1) {
        int v = __shfl_up_sync(0xffffffffu, x, o);
        if (lane >= o) x += v;
    }
    if (lane == 31) wtot[g][hw] = x;
    __syncthreads();
    int excl = x - pc + (hw ? wtot[g][0] : 0);
    int cnt  = wtot[g][0] + wtot[g][1];

    {
        int p = excl;
        uint32_t m = a;
        while (m) {
            int b = __ffs(m) - 1; m &= m - 1;
            nbr[g][p++] = (uint16_t)((w << 5) + b);
        }
    }
    __syncthreads();

    uint32_t acc = a;
    const uint16_t* nl = nbr[g];
    int j = 0;
    for (; j + 8 <= cnt; j += 8) {
        uint32_t v0 = g_adj[(int)nl[j+0] * W + w];
        uint32_t v1 = g_adj[(int)nl[j+1] * W + w];
        uint32_t v2 = g_adj[(int)nl[j+2] * W + w];
        uint32_t v3 = g_adj[(int)nl[j+3] * W + w];
        uint32_t v4 = g_adj[(int)nl[j+4] * W + w];
        uint32_t v5 = g_adj[(int)nl[j+5] * W + w];
        uint32_t v6 = g_adj[(int)nl[j+6] * W + w];
        uint32_t v7 = g_adj[(int)nl[j+7] * W + w];
        acc |= (v0 | v1) | (v2 | v3) | ((v4 | v5) | (v6 | v7));
    }
    for (; j < cnt; j++)
        acc |= g_adj[(int)nl[j] * W + w];

    uint32_t self = (w == (r >> 5)) ? (1u << (r & 31)) : 0u;
    uint32_t comb = a | (acc & ~self);
    g_comb[r * W + w] = comb;

    // word-scan of comb popcounts -> row-local word offsets + rowcnt (free)
    int epc = __popc(comb);
    int ex = epc;
    #pragma unroll
    for (int o = 1; o < 32; o <<= 1) {
        int v = __shfl_up_sync(0xffffffffu, ex, o);
        if (lane >= o) ex += v;
    }
    if (lane == 31) etot[g][hw] = ex;
    __syncthreads();
    int wexcl = ex - epc + (hw ? etot[g][0] : 0);
    g_wordexcl[r * W + w] = wexcl;
    if (w == 0) g_rowcnt[r] = etot[g][0] + etot[g][1];

    // ---- last-arriving block computes the global row-offset scan ----------
    __threadfence();
    __syncthreads();
    if (tid == 0) {
        int v = atomicAdd(&g_ctr, 1);
        islast = (v == EB - 1);
        if (islast) g_ctr = 0;           // reset for next launch
    }
    __syncthreads();
    if (!islast) return;
    __threadfence();                     // acquire side

    // scan 2048 rowcnt with 256 threads (8 each)
    int base = tid << 3;
    int loc[8];
    int s = 0;
    #pragma unroll
    for (int k = 0; k < 8; k++) { loc[k] = g_rowcnt[base + k]; s += loc[k]; }

    int incl = s;
    #pragma unroll
    for (int o = 1; o < 32; o <<= 1) {
        int v = __shfl_up_sync(0xffffffffu, incl, o);
        if ((tid & 31) >= o) incl += v;
    }
    if ((tid & 31) == 31) swarp[tid >> 5] = incl;
    __syncthreads();
    if (tid == 0) {
        int run = 0;
        #pragma unroll
        for (int q = 0; q < 8; q++) { int t = swarp[q]; swarp[q] = run; run += t; }
        g_off[NN] = run;
    }
    __syncthreads();
    int rexcl = swarp[tid >> 5] + incl - s;
    #pragma unroll
    for (int k = 0; k < 8; k++) { g_off[base + k] = rexcl; rexcl += loc[k]; }
}

// ---------------------------------------------------------------------------
// emit: 4 rows/block; stage cols in shared, coalesced streaming copy-out.
// Reads g_off / g_wordexcl directly — no prefix work, no tail.
// ---------------------------------------------------------------------------
__global__ __launch_bounds__(256) void k_emit(float* __restrict__ out, int emax)
{
    __shared__ float sbuf[4 * NN];       // staged col values (32 KB)
    __shared__ int soff[5];

    const int tid = threadIdx.x;
    const int g   = tid >> 6;
    const int w   = tid & 63;
    const int r0  = blockIdx.x << 2;
    const int r   = r0 + g;

    uint32_t comb = g_comb[r * W + w];
    int wexcl     = g_wordexcl[r * W + w];
    if (tid < 5) soff[tid] = g_off[r0 + tid];
    __syncthreads();

    // stage col values at block-local positions
    {
        int lp = (soff[g] - soff[0]) + wexcl;
        uint32_t c = comb;
        while (c) {
            int b = __ffs(c) - 1; c &= c - 1;
            sbuf[lp++] = (float)((w << 5) + b);
        }
    }
    __syncthreads();

    int gb   = soff[0];
    int c1   = soff[1] - gb;
    int c2   = soff[2] - gb;
    int c3   = soff[3] - gb;
    int bsum = soff[4] - gb;
    float* rows = out;
    float* cols = out + emax;
    float fr0 = (float)r0;
    for (int i = tid; i < bsum; i += 256) {
        int p = gb + i;
        if (p >= emax) break;
        float fr = fr0 + (float)((i >= c1) + (i >= c2) + (i >= c3));
        __stcs(rows + p, fr);
        __stcs(cols + p, sbuf[i]);
    }
}

// ---------------------------------------------------------------------------
// attr_tail (side stream, after expand): edge REDs + idx tail fill + g_adj
// re-zero. Runs concurrently with k_emit (disjoint output regions).
// ---------------------------------------------------------------------------
__global__ __launch_bounds__(256) void k_attr_tail(
    const int* __restrict__ src, const int* __restrict__ dst,
    const float* __restrict__ attr, float* __restrict__ out,
    int emax, int E)
{
    const int t   = blockIdx.x * blockDim.x + threadIdx.x;
    const int nth = gridDim.x * blockDim.x;

    if (t * 4 < NN * W)
        ((uint4*)g_adj)[t] = make_uint4(0u, 0u, 0u, 0u);

    if (t < E) {
        int s = src[t], d = dst[t];
        const float4* ia = (const float4*)(attr + (int64_t)t * FDIM);
        float4 a0 = ia[0];
        float4 a1 = ia[1];

        int idx = s * W + (d >> 5);
        int p = g_off[s] + g_wordexcl[idx]
              + __popc(g_comb[idx] & ((1u << (d & 31)) - 1u));
        if (p < emax) {
            float* oa = out + (int64_t)emax * 2 + (int64_t)p * FDIM;
            asm volatile("red.global.add.v4.f32 [%0], {%1,%2,%3,%4};"
                         :: "l"(oa), "f"(a0.x), "f"(a0.y), "f"(a0.z), "f"(a0.w)
                         : "memory");
            asm volatile("red.global.add.v4.f32 [%0], {%1,%2,%3,%4};"
                         :: "l"(oa + 4), "f"(a1.x), "f"(a1.y), "f"(a1.z), "f"(a1.w)
                         : "memory");
        }
    }

    // ---- idx tail fill [count, emax) = -1 ----------------------------------
    float* rows = out;
    float* cols = out + emax;
    int total = g_off[NN];
    if (total > emax) total = emax;
    int a0i = (total + 3) & ~3;
    if (a0i > emax) a0i = emax;
    if (t < (a0i - total)) {
        rows[total + t] = -1.f;
        cols[total + t] = -1.f;
    }
    int n4 = (emax - a0i) >> 2;
    const float4 neg = make_float4(-1.f, -1.f, -1.f, -1.f);
    float4* r4 = (float4*)(rows + a0i);
    float4* c4 = (float4*)(cols + a0i);
    for (int i = t; i < n4; i += nth) {
        __stcs(r4 + i, neg);
        __stcs(c4 + i, neg);
    }
}

// ---------------------------------------------------------------------------
// Host-side resources (host objects only; created once at process start)
// ---------------------------------------------------------------------------
static cudaStream_t s_side;
static cudaEvent_t  ev_fork, ev_expand, ev_attr;
struct _ResInit {
    _ResInit() {
        cudaStreamCreateWithFlags(&s_side, cudaStreamNonBlocking);
        cudaEventCreateWithFlags(&ev_fork,   cudaEventDisableTiming);
        cudaEventCreateWithFlags(&ev_expand, cudaEventDisableTiming);
        cudaEventCreateWithFlags(&ev_attr,   cudaEventDisableTiming);
    }
};
static _ResInit _res_init_once;

extern "C" void kernel_launch(void* const* d_in, const int* in_sizes, int n_in,
                              void* d_out, int out_size)
{
    const int*   ei   = (const int*)d_in[1];
    const float* attr = (const float*)d_in[2];
    const int E    = in_sizes[1] / 2;
    const int emax = out_size / (2 + FDIM);
    float* out = (float*)d_out;

    // side: zero attr region (overlaps with scatter+expand)
    cudaEventRecord(ev_fork, 0);
    cudaStreamWaitEvent(s_side, ev_fork, 0);
    k_init_attr<<<1024, 256, 0, s_side>>>(out, emax);

    // main: scatter -> expand (incl. g_off scan in last block)
    k_scatter<<<(E + 255) / 256, 256>>>(ei, ei + E, E);
    k_expand <<<EB, 256>>>();
    cudaEventRecord(ev_expand, 0);

    // main: emit rows   ||   side: attr REDs + tail fill (after expand+init)
    k_emit<<<EB, 256>>>(out, emax);
    cudaStreamWaitEvent(s_side, ev_expand, 0);
    k_attr_tail<<<512, 256, 0, s_side>>>(ei, ei + E, attr, out, emax, E);
    cudaEventRecord(ev_attr, s_side);

    cudaStreamWaitEvent(0, ev_attr, 0);
}